// round 14
// baseline (speedup 1.0000x reference)
#include <cuda_runtime.h>
#include <float.h>

// _VQ_29609504538631 : fused VQ-VAE bottleneck
// R13: MIO-diet restructure. 4 tokens per thread, SL=4 code/channel slicing.
//   - z via LDG.128 (4 adjacent t), out via STG.128 (LSU cost/token -61%)
//   - weight/codebook LDS serve 4 tokens (halved per token)
//   - fp64 partial merge via 3-stage smem chain (deterministic order)
//   - 8 candidates/token (top-2 x 4 slices), per-slice fp64 rescore, global
//     fp64 argmax with lowest-k tie-break (stronger than R12's 4-cand net)
// Chunk-64 fp32 sums bit-identical to R12 (same chunk boundaries); fp64
// re-association only (~1e-16) => ids preserved.

namespace {
constexpr int Bb = 8;
constexpr int Cc = 1024;
constexpr int Tt = 8192;
constexpr int Kk = 1024;
constexpr int Dd = 8;
constexpr int SL = 4;                 // slices per token
constexpr int QD = 64;                // quads per block
constexpr int NT = 256;               // threads per block
constexpr int TT = 256;               // tokens per block (64 quads x 4)
constexpr int CH = Cc / SL;           // 256 channels per slice
constexpr int KH = Kk / SL;           // 256 codes per slice
constexpr int CHUNK = 64;             // fp32 accumulation chunk (validated)
}

typedef unsigned long long u64;

__device__ __forceinline__ u64 pk2(float lo, float hi) {
    u64 r; asm("mov.b64 %0, {%1,%2};" : "=l"(r) : "f"(lo), "f"(hi)); return r;
}
__device__ __forceinline__ void upk2(u64 v, float& lo, float& hi) {
    asm("mov.b64 {%0,%1}, %2;" : "=f"(lo), "=f"(hi) : "l"(v));
}
__device__ __forceinline__ u64 ffma2(u64 a, u64 b, u64 c) {
    u64 r; asm("fma.rn.f32x2 %0, %1, %2, %3;" : "=l"(r) : "l"(a), "l"(b), "l"(c)); return r;
}

__global__ __launch_bounds__(NT, 2) void vq_fused(
    const float* __restrict__ z,
    const float* __restrict__ in_w,    // [D, C]
    const float* __restrict__ in_b,    // [D]
    const float* __restrict__ cb,      // [K, D]
    const float* __restrict__ out_w,   // [C, D]
    const float* __restrict__ out_b,   // [C]
    float* __restrict__ out,           // [B, C, T]
    float* __restrict__ ids_out)       // [B, T] (as float), may be null
{
    __shared__ __align__(16) float buf[Dd * Cc];    // 32 KB: in_w->cb->out_w
    __shared__ __align__(16) u64   aux2[Kk];        // 8 KB
    __shared__ __align__(16) char  pool[32768];     // 32 KB union (see below)
    __shared__ float bias_in[Dd];

    // pool overlays (barrier-separated lifetimes):
    //  phase-1 merge: exch0 = pool[0:16K)  (doubles [QD][4][Dd])
    //                 exch1 = pool[16K:32K)
    //  e32 broadcast: ebuf  = pool[0:8K)   (floats  [QD][4][Dd])
    //  phase-2 cands: cand  = pool[0:32K)  (double2 [SL][QD][4][2])
    double*  exch0 = reinterpret_cast<double*>(pool);
    double*  exch1 = reinterpret_cast<double*>(pool + 16384);
    float*   ebuf  = reinterpret_cast<float*>(pool);
    double2* cand  = reinterpret_cast<double2*>(pool);

    const int tid   = threadIdx.x;
    const int slice = tid >> 6;          // 0..3
    const int qr    = tid & (QD - 1);    // quad index in block
    const int b     = blockIdx.x >> 5;               // 32 blocks per batch
    const int t0    = ((blockIdx.x & 31) * TT) + 4 * qr;

    // ---- Phase 0: stage in_w transposed -> buf[c*8+d]
    for (int i = tid; i < Dd * Cc; i += NT) {
        int d = i & 7, c = i >> 3;
        buf[i] = in_w[d * Cc + c];
    }
    if (tid < Dd) bias_in[tid] = in_b[tid];
    __syncthreads();

    // ---- Phase 1: partial e over this slice's 256 channels, 4 tokens.
    double p[4][Dd];
    #pragma unroll
    for (int tk = 0; tk < 4; tk++)
        #pragma unroll
        for (int d = 0; d < Dd; d++) p[tk][d] = 0.0;

    const float* zp = z + (size_t)b * Cc * Tt + t0;
    const int cbeg = slice * CH;
    for (int c0 = cbeg; c0 < cbeg + CH; c0 += CHUNK) {
        u64 acc[4][4];
        #pragma unroll
        for (int tk = 0; tk < 4; tk++)
            #pragma unroll
            for (int j = 0; j < 4; j++) acc[tk][j] = 0ull;
        #pragma unroll 8
        for (int cc = 0; cc < CHUNK; cc++) {
            int c = c0 + cc;
            float4 v4 = __ldg(reinterpret_cast<const float4*>(zp + (size_t)c * Tt));
            u64 v0 = pk2(v4.x, v4.x);
            u64 v1 = pk2(v4.y, v4.y);
            u64 v2 = pk2(v4.z, v4.z);
            u64 v3 = pk2(v4.w, v4.w);
            const ulonglong2* wp = reinterpret_cast<const ulonglong2*>(buf + c * 8);
            ulonglong2 wA = wp[0];
            ulonglong2 wB = wp[1];
            acc[0][0] = ffma2(v0, wA.x, acc[0][0]);
            acc[0][1] = ffma2(v0, wA.y, acc[0][1]);
            acc[0][2] = ffma2(v0, wB.x, acc[0][2]);
            acc[0][3] = ffma2(v0, wB.y, acc[0][3]);
            acc[1][0] = ffma2(v1, wA.x, acc[1][0]);
            acc[1][1] = ffma2(v1, wA.y, acc[1][1]);
            acc[1][2] = ffma2(v1, wB.x, acc[1][2]);
            acc[1][3] = ffma2(v1, wB.y, acc[1][3]);
            acc[2][0] = ffma2(v2, wA.x, acc[2][0]);
            acc[2][1] = ffma2(v2, wA.y, acc[2][1]);
            acc[2][2] = ffma2(v2, wB.x, acc[2][2]);
            acc[2][3] = ffma2(v2, wB.y, acc[2][3]);
            acc[3][0] = ffma2(v3, wA.x, acc[3][0]);
            acc[3][1] = ffma2(v3, wA.y, acc[3][1]);
            acc[3][2] = ffma2(v3, wB.x, acc[3][2]);
            acc[3][3] = ffma2(v3, wB.y, acc[3][3]);
        }
        #pragma unroll
        for (int tk = 0; tk < 4; tk++)
            #pragma unroll
            for (int j = 0; j < 4; j++) {
                float lo, hi;
                upk2(acc[tk][j], lo, hi);
                p[tk][2*j]   += (double)lo;
                p[tk][2*j+1] += (double)hi;
            }
    }

    // ---- 3-stage deterministic fp64 merge: tot = (p0+p1) + (p2+p3) + bias
    const int eidx = (qr * 4) * Dd;     // base [qr][0][0]
    if (slice == 1) {
        #pragma unroll
        for (int tk = 0; tk < 4; tk++)
            #pragma unroll
            for (int d = 0; d < Dd; d++) exch0[eidx + tk*Dd + d] = p[tk][d];
    } else if (slice == 3) {
        #pragma unroll
        for (int tk = 0; tk < 4; tk++)
            #pragma unroll
            for (int d = 0; d < Dd; d++) exch1[eidx + tk*Dd + d] = p[tk][d];
    }
    __syncthreads();
    if (slice == 0) {
        #pragma unroll
        for (int tk = 0; tk < 4; tk++)
            #pragma unroll
            for (int d = 0; d < Dd; d++)
                p[tk][d] = p[tk][d] + exch0[eidx + tk*Dd + d];   // p0+p1
    } else if (slice == 2) {
        #pragma unroll
        for (int tk = 0; tk < 4; tk++)
            #pragma unroll
            for (int d = 0; d < Dd; d++)
                exch1[eidx + tk*Dd + d] = p[tk][d] + exch1[eidx + tk*Dd + d]; // p2+p3
    }
    __syncthreads();
    if (slice == 0) {
        #pragma unroll
        for (int tk = 0; tk < 4; tk++)
            #pragma unroll
            for (int d = 0; d < Dd; d++) {
                double tot = p[tk][d] + exch1[eidx + tk*Dd + d];
                ebuf[eidx + tk*Dd + d] = (float)(tot + (double)bias_in[d]);
            }
    }
    __syncthreads();

    // all threads pick up e32 as packed d-pairs: ep[tok][j]
    u64 ep[4][4];
    {
        const ulonglong2* eb = reinterpret_cast<const ulonglong2*>(ebuf + eidx);
        #pragma unroll
        for (int tk = 0; tk < 4; tk++) {
            ulonglong2 a = eb[tk*2], bb = eb[tk*2+1];
            ep[tk][0] = a.x;  ep[tk][1] = a.y;
            ep[tk][2] = bb.x; ep[tk][3] = bb.y;
        }
    }

    // ---- Phase 2a: stage codebook + pre-paired (-0.5||w||^2, 0)
    for (int k = tid; k < Kk; k += NT) {
        float4 c0 = __ldg(reinterpret_cast<const float4*>(cb + k * 8));
        float4 c1 = __ldg(reinterpret_cast<const float4*>(cb + k * 8) + 1);
        reinterpret_cast<float4*>(buf)[k * 2]     = c0;
        reinterpret_cast<float4*>(buf)[k * 2 + 1] = c1;
        double n = (double)c0.x*c0.x + (double)c0.y*c0.y
                 + (double)c0.z*c0.z + (double)c0.w*c0.w
                 + (double)c1.x*c1.x + (double)c1.y*c1.y
                 + (double)c1.z*c1.z + (double)c1.w*c1.w;
        aux2[k] = pk2(-(float)(0.5 * n), 0.0f);
    }
    __syncthreads();   // also orders all ebuf reads before cand overwrites pool

    // ---- Phase 2b: scan this slice's 256 codes in groups of 4, 4 tokens.
    float b1[4], b2[4];
    int   i1[4], i2[4];
    #pragma unroll
    for (int tk = 0; tk < 4; tk++) {
        b1[tk] = -FLT_MAX; b2[tk] = -FLT_MAX;
        i1[tk] = slice * KH; i2[tk] = slice * KH;
    }
    const int kbeg = slice * KH;
    #pragma unroll 2
    for (int k = kbeg; k < kbeg + KH; k += 4) {
        const ulonglong2* wp = reinterpret_cast<const ulonglong2*>(buf + k * 8);
        ulonglong2 iab01 = *reinterpret_cast<const ulonglong2*>(&aux2[k]);
        ulonglong2 iab23 = *reinterpret_cast<const ulonglong2*>(&aux2[k + 2]);

        ulonglong2 wa0 = wp[0], wa1 = wp[1];   // code k
        ulonglong2 wb0 = wp[2], wb1 = wp[3];   // code k+1
        float sa[4], sb[4];
        #pragma unroll
        for (int tk = 0; tk < 4; tk++) {
            u64 da = ffma2(ep[tk][3], wa1.y, ffma2(ep[tk][2], wa1.x,
                     ffma2(ep[tk][1], wa0.y, ffma2(ep[tk][0], wa0.x, iab01.x))));
            u64 db = ffma2(ep[tk][3], wb1.y, ffma2(ep[tk][2], wb1.x,
                     ffma2(ep[tk][1], wb0.y, ffma2(ep[tk][0], wb0.x, iab01.y))));
            float lo, hi;
            upk2(da, lo, hi); sa[tk] = lo + hi;
            upk2(db, lo, hi); sb[tk] = lo + hi;
        }
        wa0 = wp[4]; wa1 = wp[5];              // code k+2
        wb0 = wp[6]; wb1 = wp[7];              // code k+3
        float sc[4], sd[4];
        #pragma unroll
        for (int tk = 0; tk < 4; tk++) {
            u64 da = ffma2(ep[tk][3], wa1.y, ffma2(ep[tk][2], wa1.x,
                     ffma2(ep[tk][1], wa0.y, ffma2(ep[tk][0], wa0.x, iab23.x))));
            u64 db = ffma2(ep[tk][3], wb1.y, ffma2(ep[tk][2], wb1.x,
                     ffma2(ep[tk][1], wb0.y, ffma2(ep[tk][0], wb0.x, iab23.y))));
            float lo, hi;
            upk2(da, lo, hi); sc[tk] = lo + hi;
            upk2(db, lo, hi); sd[tk] = lo + hi;
        }
        #pragma unroll
        for (int tk = 0; tk < 4; tk++) {
            bool pa = sa[tk] >= sb[tk];
            float s01 = pa ? sa[tk] : sb[tk];  int k01 = pa ? k : k + 1;
            bool pb = sc[tk] >= sd[tk];
            float s23 = pb ? sc[tk] : sd[tk];  int k23 = pb ? k + 2 : k + 3;
            bool pc = s01 >= s23;
            float sm = pc ? s01 : s23;         int km = pc ? k01 : k23;
            bool q2 = sm > b2[tk];
            float c2 = q2 ? sm : b2[tk];       int j2 = q2 ? km : i2[tk];
            bool q1 = sm > b1[tk];
            b2[tk] = q1 ? b1[tk] : c2;         i2[tk] = q1 ? i1[tk] : j2;
            b1[tk] = q1 ? sm : b1[tk];         i1[tk] = q1 ? km : i1[tk];
        }
    }

    // ---- per-slice fp64 rescore of own 2 candidates per token -> cand pool
    #pragma unroll
    for (int tk = 0; tk < 4; tk++) {
        float e32[Dd];
        #pragma unroll
        for (int j = 0; j < 4; j++) upk2(ep[tk][j], e32[2*j], e32[2*j+1]);
        #pragma unroll
        for (int j = 0; j < 2; j++) {
            int kc = j ? i2[tk] : i1[tk];
            const float* w = buf + kc * 8;
            double dot = 0.0, nrm = 0.0;
            #pragma unroll
            for (int i = 0; i < Dd; i++) {
                double wi = (double)w[i];
                dot += (double)e32[i] * wi;
                nrm += wi * wi;
            }
            cand[((slice * QD + qr) * 4 + tk) * 2 + j] =
                make_double2(dot - 0.5 * nrm, (double)kc);
        }
    }
    __syncthreads();

    // ---- global fp64 argmax over 8 candidates per token (lowest k on ties)
    int bi[4];
    #pragma unroll
    for (int tk = 0; tk < 4; tk++) {
        double bs = -DBL_MAX;
        int    bk = Kk;
        #pragma unroll
        for (int s = 0; s < SL; s++)
            #pragma unroll
            for (int j = 0; j < 2; j++) {
                double2 cd = cand[((s * QD + qr) * 4 + tk) * 2 + j];
                int kc = (int)cd.y;
                if (cd.x > bs || (cd.x == bs && kc < bk)) { bs = cd.x; bk = kc; }
            }
        bi[tk] = bk;
    }

    // grab winning codes before buf is overwritten
    u64 qp[4][4];
    #pragma unroll
    for (int tk = 0; tk < 4; tk++) {
        const ulonglong2* w = reinterpret_cast<const ulonglong2*>(buf + bi[tk] * 8);
        ulonglong2 x0 = w[0], x1 = w[1];
        qp[tk][0] = x0.x; qp[tk][1] = x0.y; qp[tk][2] = x1.x; qp[tk][3] = x1.y;
    }
    __syncthreads();   // codebook reads done

    // ---- Phase 3a: stage out_w ([C,D] already c*8+d); aux2 <- (out_b, 0)
    for (int i = tid; i < Cc * Dd; i += NT) buf[i] = out_w[i];
    for (int i = tid; i < Cc; i += NT)      aux2[i] = pk2(out_b[i], 0.0f);
    __syncthreads();

    // ---- Phase 3b: this slice writes channels [cbeg, cbeg+256), 4 tokens.
    float* op = out + (size_t)b * Cc * Tt + t0;
    #pragma unroll 4
    for (int c = cbeg; c < cbeg + CH; c++) {
        const ulonglong2* wp = reinterpret_cast<const ulonglong2*>(buf + c * 8);
        ulonglong2 wA = wp[0], wB = wp[1];
        u64 ic = aux2[c];
        float s[4];
        #pragma unroll
        for (int tk = 0; tk < 4; tk++) {
            u64 dd = ffma2(qp[tk][3], wB.y, ffma2(qp[tk][2], wB.x,
                     ffma2(qp[tk][1], wA.y, ffma2(qp[tk][0], wA.x, ic))));
            float lo, hi;
            upk2(dd, lo, hi);
            s[tk] = lo + hi;
        }
        *reinterpret_cast<float4*>(op + (size_t)c * Tt) =
            make_float4(s[0], s[1], s[2], s[3]);
    }

    if (slice == 0 && ids_out) {
        *reinterpret_cast<float4*>(ids_out + (size_t)b * Tt + t0) =
            make_float4((float)bi[0], (float)bi[1], (float)bi[2], (float)bi[3]);
    }
}

extern "C" void kernel_launch(void* const* d_in, const int* in_sizes, int n_in,
                              void* d_out, int out_size) {
    const float* z     = (const float*)d_in[0];
    const float* in_w  = (const float*)d_in[1];
    const float* in_b  = (const float*)d_in[2];
    const float* cb    = (const float*)d_in[3];
    const float* out_w = (const float*)d_in[4];
    const float* out_b = (const float*)d_in[5];

    float* out = (float*)d_out;
    const long long out_elems = (long long)Bb * Cc * Tt;
    float* ids = (out_size > out_elems) ? out + out_elems : nullptr;

    dim3 grid(Bb * (Tt / TT));   // 256 blocks x 256 threads, 4 tokens/thread
    vq_fused<<<grid, NT>>>(z, in_w, in_b, cb, out_w, out_b, out, ids);
}

// round 15
// speedup vs baseline: 1.2244x; 1.2244x over previous
#include <cuda_runtime.h>
#include <float.h>

// _VQ_29609504538631 : fused VQ-VAE bottleneck
// R14: hybrid remap. Phase 1 = R12 verbatim (2 tok/thread, SL=2; proven regs).
// Phases 2+3 remapped to 4 tok/thread (64 quads x 4 slices) via ebuf smem:
//   - phase-2 LDS per token halves (w fetch serves 4 tokens)
//   - phase-3: 256 c-iters with STG.128 (was 512 with STG.64)
//   - 8 fp64-rescored candidates/token (top-2 x 4 slices), lowest-k ties
// e32 bit-identical to R12 (same fp32 chunk sums + same fp64 merge order).

namespace {
constexpr int Bb = 8;
constexpr int Cc = 1024;
constexpr int Tt = 8192;
constexpr int Kk = 1024;
constexpr int Dd = 8;
constexpr int TT  = 256;              // tokens per block
constexpr int NT  = 256;              // threads per block
// phase 1 mapping (R12): token pairs
constexpr int NP  = 128;              // pairs per block
constexpr int CH1 = 512;              // channels per phase-1 slice
constexpr int CHUNK = 64;             // fp32 accumulation chunk (validated)
// phase 2/3 mapping: token quads
constexpr int QD  = 64;               // quads per block
constexpr int SL  = 4;                // slices
constexpr int KH  = Kk / SL;          // 256 codes per slice
constexpr int CH3 = Cc / SL;          // 256 channels per slice
}

typedef unsigned long long u64;

__device__ __forceinline__ u64 pk2(float lo, float hi) {
    u64 r; asm("mov.b64 %0, {%1,%2};" : "=l"(r) : "f"(lo), "f"(hi)); return r;
}
__device__ __forceinline__ void upk2(u64 v, float& lo, float& hi) {
    asm("mov.b64 {%0,%1}, %2;" : "=f"(lo), "=f"(hi) : "l"(v));
}
__device__ __forceinline__ u64 ffma2(u64 a, u64 b, u64 c) {
    u64 r; asm("fma.rn.f32x2 %0, %1, %2, %3;" : "=l"(r) : "l"(a), "l"(b), "l"(c)); return r;
}

__global__ __launch_bounds__(NT, 2) void vq_fused(
    const float* __restrict__ z,
    const float* __restrict__ in_w,    // [D, C]
    const float* __restrict__ in_b,    // [D]
    const float* __restrict__ cb,      // [K, D]
    const float* __restrict__ out_w,   // [C, D]
    const float* __restrict__ out_b,   // [C]
    float* __restrict__ out,           // [B, C, T]
    float* __restrict__ ids_out)       // [B, T] (as float), may be null
{
    __shared__ __align__(16) float buf[Dd * Cc];    // 32 KB: in_w->cb->out_w
    __shared__ __align__(16) u64   aux2[Kk];        // 8 KB
    __shared__ __align__(16) char  pool[32768];     // exch (16K) / cand (32K)
    __shared__ __align__(16) float ebuf[TT * Dd];   // 8 KB: e32 per token
    __shared__ float bias_in[Dd];

    double*  exch = reinterpret_cast<double*>(pool);    // [NP][2][Dd] slice-1 partials
    double2* cand = reinterpret_cast<double2*>(pool);   // [SL][QD][4][2]

    const int tid = threadIdx.x;
    const int b   = blockIdx.x >> 5;                 // 32 blocks per batch
    const int tbase = (blockIdx.x & 31) * TT;

    // phase-1 ids (R12 mapping)
    const int slice1 = tid >> 7;          // 0/1
    const int pr     = tid & (NP - 1);
    const int t0     = tbase + 2 * pr;
    // phase-2/3 ids (quad mapping)
    const int slc  = tid >> 6;            // 0..3
    const int quad = tid & (QD - 1);
    const int tq0  = tbase + 4 * quad;

    // ---- Phase 0: stage in_w transposed -> buf[c*8+d]
    for (int i = tid; i < Dd * Cc; i += NT) {
        int d = i & 7, c = i >> 3;
        buf[i] = in_w[d * Cc + c];
    }
    if (tid < Dd) bias_in[tid] = in_b[tid];
    __syncthreads();

    // ---- Phase 1 (R12 verbatim): partial e over 512 channels, 2 tokens.
    double p0[Dd], p1[Dd];
    #pragma unroll
    for (int d = 0; d < Dd; d++) { p0[d] = 0.0; p1[d] = 0.0; }

    const float* zp = z + (size_t)b * Cc * Tt + t0;
    const int cbeg1 = slice1 * CH1;
    for (int c0 = cbeg1; c0 < cbeg1 + CH1; c0 += CHUNK) {
        u64 a0[4], a1[4];
        #pragma unroll
        for (int j = 0; j < 4; j++) { a0[j] = 0ull; a1[j] = 0ull; }
        #pragma unroll 16
        for (int cc = 0; cc < CHUNK; cc++) {
            int c = c0 + cc;
            float2 v2 = __ldg(reinterpret_cast<const float2*>(zp + (size_t)c * Tt));
            u64 v0 = pk2(v2.x, v2.x);
            u64 v1 = pk2(v2.y, v2.y);
            const ulonglong2* wp = reinterpret_cast<const ulonglong2*>(buf + c * 8);
            ulonglong2 wA = wp[0];
            ulonglong2 wB = wp[1];
            a0[0] = ffma2(v0, wA.x, a0[0]);
            a0[1] = ffma2(v0, wA.y, a0[1]);
            a0[2] = ffma2(v0, wB.x, a0[2]);
            a0[3] = ffma2(v0, wB.y, a0[3]);
            a1[0] = ffma2(v1, wA.x, a1[0]);
            a1[1] = ffma2(v1, wA.y, a1[1]);
            a1[2] = ffma2(v1, wB.x, a1[2]);
            a1[3] = ffma2(v1, wB.y, a1[3]);
        }
        #pragma unroll
        for (int j = 0; j < 4; j++) {
            float lo, hi;
            upk2(a0[j], lo, hi); p0[2*j] += (double)lo; p0[2*j+1] += (double)hi;
            upk2(a1[j], lo, hi); p1[2*j] += (double)lo; p1[2*j+1] += (double)hi;
        }
    }
    // slice 1 publishes partials; slice 0 merges (order: s0 + s1, as R12)
    if (slice1 == 1) {
        #pragma unroll
        for (int d = 0; d < Dd; d++) {
            exch[(pr * 2 + 0) * Dd + d] = p0[d];
            exch[(pr * 2 + 1) * Dd + d] = p1[d];
        }
    }
    __syncthreads();
    if (slice1 == 0) {
        #pragma unroll
        for (int d = 0; d < Dd; d++) {
            double s0 = p0[d] + exch[(pr * 2 + 0) * Dd + d];
            double s1 = p1[d] + exch[(pr * 2 + 1) * Dd + d];
            ebuf[(2 * pr)     * Dd + d] = (float)(s0 + (double)bias_in[d]);
            ebuf[(2 * pr + 1) * Dd + d] = (float)(s1 + (double)bias_in[d]);
        }
    }
    __syncthreads();

    // ---- pick up e32 for this thread's QUAD as packed d-pairs
    u64 ep[4][4];
    {
        const ulonglong2* eb = reinterpret_cast<const ulonglong2*>(ebuf + 4 * quad * Dd);
        #pragma unroll
        for (int tk = 0; tk < 4; tk++) {
            ulonglong2 a = eb[tk * 2], bb = eb[tk * 2 + 1];
            ep[tk][0] = a.x;  ep[tk][1] = a.y;
            ep[tk][2] = bb.x; ep[tk][3] = bb.y;
        }
    }

    // ---- Phase 2a: stage codebook + pre-paired (-0.5||w||^2, 0)
    for (int k = tid; k < Kk; k += NT) {
        float4 c0 = __ldg(reinterpret_cast<const float4*>(cb + k * 8));
        float4 c1 = __ldg(reinterpret_cast<const float4*>(cb + k * 8) + 1);
        reinterpret_cast<float4*>(buf)[k * 2]     = c0;
        reinterpret_cast<float4*>(buf)[k * 2 + 1] = c1;
        double n = (double)c0.x*c0.x + (double)c0.y*c0.y
                 + (double)c0.z*c0.z + (double)c0.w*c0.w
                 + (double)c1.x*c1.x + (double)c1.y*c1.y
                 + (double)c1.z*c1.z + (double)c1.w*c1.w;
        aux2[k] = pk2(-(float)(0.5 * n), 0.0f);
    }
    __syncthreads();   // exch dead after this; cand may overwrite pool later

    // ---- Phase 2b: scan this slice's 256 codes in PAIRS for 4 tokens.
    float b1[4], b2[4];
    int   i1[4], i2[4];
    #pragma unroll
    for (int tk = 0; tk < 4; tk++) {
        b1[tk] = -FLT_MAX; b2[tk] = -FLT_MAX;
        i1[tk] = slc * KH; i2[tk] = slc * KH;
    }
    const int kbeg = slc * KH;
    #pragma unroll 4
    for (int k = kbeg; k < kbeg + KH; k += 2) {
        const ulonglong2* wp = reinterpret_cast<const ulonglong2*>(buf + k * 8);
        ulonglong2 wa0 = wp[0], wa1 = wp[1];   // code k
        ulonglong2 wb0 = wp[2], wb1 = wp[3];   // code k+1
        ulonglong2 iab = *reinterpret_cast<const ulonglong2*>(&aux2[k]);
        #pragma unroll
        for (int tk = 0; tk < 4; tk++) {
            u64 da = ffma2(ep[tk][3], wa1.y, ffma2(ep[tk][2], wa1.x,
                     ffma2(ep[tk][1], wa0.y, ffma2(ep[tk][0], wa0.x, iab.x))));
            u64 db = ffma2(ep[tk][3], wb1.y, ffma2(ep[tk][2], wb1.x,
                     ffma2(ep[tk][1], wb0.y, ffma2(ep[tk][0], wb0.x, iab.y))));
            float lo, hi;
            upk2(da, lo, hi); float sa = lo + hi;
            upk2(db, lo, hi); float sb = lo + hi;
            bool pa = sa >= sb;                       // ties -> lower k
            float sm = pa ? sa : sb;
            int   km = pa ? k : k + 1;
            bool q2 = sm > b2[tk];
            float c2 = q2 ? sm : b2[tk];  int j2 = q2 ? km : i2[tk];
            bool q1 = sm > b1[tk];
            b2[tk] = q1 ? b1[tk] : c2;    i2[tk] = q1 ? i1[tk] : j2;
            b1[tk] = q1 ? sm : b1[tk];    i1[tk] = q1 ? km : i1[tk];
        }
    }

    // ---- per-slice fp64 rescore of own 2 candidates per token -> cand pool
    #pragma unroll
    for (int tk = 0; tk < 4; tk++) {
        float e32[Dd];
        #pragma unroll
        for (int j = 0; j < 4; j++) upk2(ep[tk][j], e32[2*j], e32[2*j+1]);
        #pragma unroll
        for (int j = 0; j < 2; j++) {
            int kc = j ? i2[tk] : i1[tk];
            const float* w = buf + kc * 8;
            double dot = 0.0, nrm = 0.0;
            #pragma unroll
            for (int i = 0; i < Dd; i++) {
                double wi = (double)w[i];
                dot += (double)e32[i] * wi;
                nrm += wi * wi;
            }
            cand[((slc * QD + quad) * 4 + tk) * 2 + j] =
                make_double2(dot - 0.5 * nrm, (double)kc);
        }
    }
    __syncthreads();

    // ---- global fp64 argmax over 8 candidates per token (lowest k on ties)
    // (all 4 slice-threads of a quad compute identically)
    int bi[4];
    #pragma unroll
    for (int tk = 0; tk < 4; tk++) {
        double bs = -DBL_MAX;
        int    bk = Kk;
        #pragma unroll
        for (int s = 0; s < SL; s++)
            #pragma unroll
            for (int j = 0; j < 2; j++) {
                double2 cd = cand[((s * QD + quad) * 4 + tk) * 2 + j];
                int kc = (int)cd.y;
                if (cd.x > bs || (cd.x == bs && kc < bk)) { bs = cd.x; bk = kc; }
            }
        bi[tk] = bk;
    }

    // grab winning codes before buf is overwritten
    u64 qp[4][4];
    #pragma unroll
    for (int tk = 0; tk < 4; tk++) {
        const ulonglong2* w = reinterpret_cast<const ulonglong2*>(buf + bi[tk] * 8);
        ulonglong2 x0 = w[0], x1 = w[1];
        qp[tk][0] = x0.x; qp[tk][1] = x0.y; qp[tk][2] = x1.x; qp[tk][3] = x1.y;
    }
    __syncthreads();   // codebook reads done

    // ---- Phase 3a: stage out_w ([C,D] already c*8+d); aux2 <- (out_b, 0)
    for (int i = tid; i < Cc * Dd; i += NT) buf[i] = out_w[i];
    for (int i = tid; i < Cc; i += NT)      aux2[i] = pk2(out_b[i], 0.0f);
    __syncthreads();

    // ---- Phase 3b: this slice writes channels [slc*256, +256), 4 tokens.
    float* op = out + (size_t)b * Cc * Tt + tq0;
    const int cbeg3 = slc * CH3;
    #pragma unroll 4
    for (int c = cbeg3; c < cbeg3 + CH3; c++) {
        const ulonglong2* wp = reinterpret_cast<const ulonglong2*>(buf + c * 8);
        ulonglong2 wA = wp[0], wB = wp[1];
        u64 ic = aux2[c];
        float s[4];
        #pragma unroll
        for (int tk = 0; tk < 4; tk++) {
            u64 dd = ffma2(qp[tk][3], wB.y, ffma2(qp[tk][2], wB.x,
                     ffma2(qp[tk][1], wA.y, ffma2(qp[tk][0], wA.x, ic))));
            float lo, hi;
            upk2(dd, lo, hi);
            s[tk] = lo + hi;
        }
        *reinterpret_cast<float4*>(op + (size_t)c * Tt) =
            make_float4(s[0], s[1], s[2], s[3]);
    }

    if (slc == 0 && ids_out) {
        *reinterpret_cast<float4*>(ids_out + (size_t)b * Tt + tq0) =
            make_float4((float)bi[0], (float)bi[1], (float)bi[2], (float)bi[3]);
    }
}

extern "C" void kernel_launch(void* const* d_in, const int* in_sizes, int n_in,
                              void* d_out, int out_size) {
    const float* z     = (const float*)d_in[0];
    const float* in_w  = (const float*)d_in[1];
    const float* in_b  = (const float*)d_in[2];
    const float* cb    = (const float*)d_in[3];
    const float* out_w = (const float*)d_in[4];
    const float* out_b = (const float*)d_in[5];

    float* out = (float*)d_out;
    const long long out_elems = (long long)Bb * Cc * Tt;
    float* ids = (out_size > out_elems) ? out + out_elems : nullptr;

    dim3 grid(Bb * (Tt / TT));   // 256 blocks x 256 threads
    vq_fused<<<grid, NT>>>(z, in_w, in_b, cb, out_w, out_b, out, ids);
}

// round 16
// speedup vs baseline: 1.3507x; 1.1031x over previous
#include <cuda_runtime.h>
#include <float.h>

// _VQ_29609504538631 : fused VQ-VAE bottleneck
// R15 = R12 (best, 173us kernel) with ONLY phase 3 remapped to token-quads:
//   - phases 0-2 + rescore: byte-identical to R12 (2 tok/thread, SL=2,
//     4-code-group scan with single top-2 update per 4 codes)
//   - winning ids published to smem ibuf; phase 3 runs as 64 quads x 4
//     slices: 4 tokens/thread, 256 channels, STG.128 (was 512 c, STG.64)
// Phase-3 ffma2 chain identical => outputs/ids bit-identical to R12.

namespace {
constexpr int Bb = 8;
constexpr int Cc = 1024;
constexpr int Tt = 8192;
constexpr int Kk = 1024;
constexpr int Dd = 8;
constexpr int TT  = 256;              // tokens per block (128 pairs)
constexpr int NP  = 128;              // token-pairs per block
constexpr int SL  = 2;                // slices per token (phases 1-2)
constexpr int NT  = NP * SL;          // 256 threads
constexpr int CH  = Cc / SL;          // 512 channels per phase-1 slice
constexpr int KH  = Kk / SL;          // 512 codes per slice
constexpr int CHUNK = 64;             // fp32 accumulation chunk (validated)
// phase-3 quad mapping
constexpr int QD  = 64;               // quads per block
constexpr int SL3 = 4;                // phase-3 channel slices
constexpr int CH3 = Cc / SL3;         // 256 channels per phase-3 slice
}

typedef unsigned long long u64;

__device__ __forceinline__ u64 pk2(float lo, float hi) {
    u64 r; asm("mov.b64 %0, {%1,%2};" : "=l"(r) : "f"(lo), "f"(hi)); return r;
}
__device__ __forceinline__ void upk2(u64 v, float& lo, float& hi) {
    asm("mov.b64 {%0,%1}, %2;" : "=f"(lo), "=f"(hi) : "l"(v));
}
__device__ __forceinline__ u64 ffma2(u64 a, u64 b, u64 c) {
    u64 r; asm("fma.rn.f32x2 %0, %1, %2, %3;" : "=l"(r) : "l"(a), "l"(b), "l"(c)); return r;
}

__global__ __launch_bounds__(NT, 2) void vq_fused(
    const float* __restrict__ z,
    const float* __restrict__ in_w,    // [D, C]
    const float* __restrict__ in_b,    // [D]
    const float* __restrict__ cb,      // [K, D]
    const float* __restrict__ out_w,   // [C, D]
    const float* __restrict__ out_b,   // [C]
    float* __restrict__ out,           // [B, C, T]
    float* __restrict__ ids_out)       // [B, T] (as float), may be null
{
    __shared__ __align__(16) float buf[Dd * Cc];    // 32 KB: in_w->cb->out_w
    __shared__ __align__(16) u64 aux2[Kk];          // 8 KB
    __shared__ double exch[SL][NP][2][Dd];          // 32 KB fp64 partials
    __shared__ int    cand_i[SL][NP][2][2];         // 4 KB candidate ids
    __shared__ int    ibuf[TT];                     // 1 KB winning ids
    __shared__ float  bias_in[Dd];

    const int tid   = threadIdx.x;
    const int slice = tid >> 7;           // 0/1
    const int pr    = tid & (NP - 1);     // pair index in block
    const int b     = blockIdx.x / (Tt / TT);
    const int tbase = (blockIdx.x % (Tt / TT)) * TT;
    const int t0    = tbase + 2 * pr;     // even
    // phase-3 quad mapping
    const int slc3  = tid >> 6;           // 0..3
    const int quad  = tid & (QD - 1);
    const int tq0   = tbase + 4 * quad;

    // ---- Phase 0: stage in_w transposed -> buf[c*8+d]
    for (int i = tid; i < Dd * Cc; i += NT) {
        int d = i & 7, c = i >> 3;
        buf[i] = in_w[d * Cc + c];
    }
    if (tid < Dd) bias_in[tid] = in_b[tid];
    __syncthreads();

    // ---- Phase 1: partial e over this slice's 512 channels, 2 tokens packed.
    double p0[Dd], p1[Dd];
    #pragma unroll
    for (int d = 0; d < Dd; d++) { p0[d] = 0.0; p1[d] = 0.0; }

    const float* zp = z + (size_t)b * Cc * Tt + t0;
    const int cbeg = slice * CH;
    for (int c0 = cbeg; c0 < cbeg + CH; c0 += CHUNK) {
        u64 a0[4], a1[4];
        #pragma unroll
        for (int j = 0; j < 4; j++) { a0[j] = 0ull; a1[j] = 0ull; }
        #pragma unroll 16
        for (int cc = 0; cc < CHUNK; cc++) {
            int c = c0 + cc;
            float2 v2 = __ldg(reinterpret_cast<const float2*>(zp + (size_t)c * Tt));
            u64 v0 = pk2(v2.x, v2.x);
            u64 v1 = pk2(v2.y, v2.y);
            const ulonglong2* wp = reinterpret_cast<const ulonglong2*>(buf + c * 8);
            ulonglong2 wA = wp[0];
            ulonglong2 wB = wp[1];
            a0[0] = ffma2(v0, wA.x, a0[0]);
            a0[1] = ffma2(v0, wA.y, a0[1]);
            a0[2] = ffma2(v0, wB.x, a0[2]);
            a0[3] = ffma2(v0, wB.y, a0[3]);
            a1[0] = ffma2(v1, wA.x, a1[0]);
            a1[1] = ffma2(v1, wA.y, a1[1]);
            a1[2] = ffma2(v1, wB.x, a1[2]);
            a1[3] = ffma2(v1, wB.y, a1[3]);
        }
        #pragma unroll
        for (int j = 0; j < 4; j++) {
            float lo, hi;
            upk2(a0[j], lo, hi); p0[2*j] += (double)lo; p0[2*j+1] += (double)hi;
            upk2(a1[j], lo, hi); p1[2*j] += (double)lo; p1[2*j+1] += (double)hi;
        }
    }
    #pragma unroll
    for (int d = 0; d < Dd; d++) {
        exch[slice][pr][0][d] = p0[d];
        exch[slice][pr][1][d] = p1[d];
    }
    __syncthreads();   // buf(in_w) reads done; partials published

    // merge partials in identical order on both slice threads
    float e0[Dd], e1[Dd];
    #pragma unroll
    for (int d = 0; d < Dd; d++) {
        e0[d] = (float)((exch[0][pr][0][d] + exch[1][pr][0][d]) + (double)bias_in[d]);
        e1[d] = (float)((exch[0][pr][1][d] + exch[1][pr][1][d]) + (double)bias_in[d]);
    }

    // ---- Phase 2a: stage codebook + pre-paired (-0.5||w||^2, 0)
    for (int k = tid; k < Kk; k += NT) {
        float4 c0 = __ldg(reinterpret_cast<const float4*>(cb + k * 8));
        float4 c1 = __ldg(reinterpret_cast<const float4*>(cb + k * 8) + 1);
        reinterpret_cast<float4*>(buf)[k * 2]     = c0;
        reinterpret_cast<float4*>(buf)[k * 2 + 1] = c1;
        double n = (double)c0.x*c0.x + (double)c0.y*c0.y
                 + (double)c0.z*c0.z + (double)c0.w*c0.w
                 + (double)c1.x*c1.x + (double)c1.y*c1.y
                 + (double)c1.z*c1.z + (double)c1.w*c1.w;
        aux2[k] = pk2(-(float)(0.5 * n), 0.0f);
    }
    __syncthreads();

    // ---- Phase 2b: scan this slice's 512 codes in groups of 4, both tokens.
    u64 ep0[4], ep1[4];
    #pragma unroll
    for (int j = 0; j < 4; j++) {
        ep0[j] = pk2(e0[2*j], e0[2*j+1]);
        ep1[j] = pk2(e1[2*j], e1[2*j+1]);
    }
    float b1t0 = -FLT_MAX, b2t0 = -FLT_MAX, b1t1 = -FLT_MAX, b2t1 = -FLT_MAX;
    int   i1t0 = slice*KH, i2t0 = slice*KH, i1t1 = slice*KH, i2t1 = slice*KH;
    const int kbeg = slice * KH;
    #pragma unroll 2
    for (int k = kbeg; k < kbeg + KH; k += 4) {
        const ulonglong2* wp = reinterpret_cast<const ulonglong2*>(buf + k * 8);
        ulonglong2 iab01 = *reinterpret_cast<const ulonglong2*>(&aux2[k]);
        ulonglong2 iab23 = *reinterpret_cast<const ulonglong2*>(&aux2[k + 2]);

        // codes k, k+1
        ulonglong2 wa0 = wp[0], wa1 = wp[1];
        ulonglong2 wb0 = wp[2], wb1 = wp[3];
        u64 da = ffma2(ep0[3], wa1.y, ffma2(ep0[2], wa1.x,
                 ffma2(ep0[1], wa0.y, ffma2(ep0[0], wa0.x, iab01.x))));
        u64 db = ffma2(ep0[3], wb1.y, ffma2(ep0[2], wb1.x,
                 ffma2(ep0[1], wb0.y, ffma2(ep0[0], wb0.x, iab01.y))));
        float lo, hi;
        upk2(da, lo, hi); float sa0 = lo + hi;
        upk2(db, lo, hi); float sb0 = lo + hi;
        da = ffma2(ep1[3], wa1.y, ffma2(ep1[2], wa1.x,
             ffma2(ep1[1], wa0.y, ffma2(ep1[0], wa0.x, iab01.x))));
        db = ffma2(ep1[3], wb1.y, ffma2(ep1[2], wb1.x,
             ffma2(ep1[1], wb0.y, ffma2(ep1[0], wb0.x, iab01.y))));
        upk2(da, lo, hi); float sa1 = lo + hi;
        upk2(db, lo, hi); float sb1 = lo + hi;

        bool pa0 = sa0 >= sb0;
        float s01_0 = pa0 ? sa0 : sb0;  int k01_0 = pa0 ? k : k + 1;
        bool pa1 = sa1 >= sb1;
        float s01_1 = pa1 ? sa1 : sb1;  int k01_1 = pa1 ? k : k + 1;

        // codes k+2, k+3 (reuse w registers)
        wa0 = wp[4]; wa1 = wp[5];
        wb0 = wp[6]; wb1 = wp[7];
        da = ffma2(ep0[3], wa1.y, ffma2(ep0[2], wa1.x,
             ffma2(ep0[1], wa0.y, ffma2(ep0[0], wa0.x, iab23.x))));
        db = ffma2(ep0[3], wb1.y, ffma2(ep0[2], wb1.x,
             ffma2(ep0[1], wb0.y, ffma2(ep0[0], wb0.x, iab23.y))));
        upk2(da, lo, hi); float sc0 = lo + hi;
        upk2(db, lo, hi); float sd0 = lo + hi;
        da = ffma2(ep1[3], wa1.y, ffma2(ep1[2], wa1.x,
             ffma2(ep1[1], wa0.y, ffma2(ep1[0], wa0.x, iab23.x))));
        db = ffma2(ep1[3], wb1.y, ffma2(ep1[2], wb1.x,
             ffma2(ep1[1], wb0.y, ffma2(ep1[0], wb0.x, iab23.y))));
        upk2(da, lo, hi); float sc1 = lo + hi;
        upk2(db, lo, hi); float sd1 = lo + hi;

        bool pb0 = sc0 >= sd0;
        float s23_0 = pb0 ? sc0 : sd0;  int k23_0 = pb0 ? k + 2 : k + 3;
        bool pb1 = sc1 >= sd1;
        float s23_1 = pb1 ? sc1 : sd1;  int k23_1 = pb1 ? k + 2 : k + 3;

        bool pc0 = s01_0 >= s23_0;
        float sm0 = pc0 ? s01_0 : s23_0;  int km0 = pc0 ? k01_0 : k23_0;
        bool pc1 = s01_1 >= s23_1;
        float sm1 = pc1 ? s01_1 : s23_1;  int km1 = pc1 ? k01_1 : k23_1;

        {
            bool q2 = sm0 > b2t0;
            float c2 = q2 ? sm0 : b2t0;  int j2 = q2 ? km0 : i2t0;
            bool q1 = sm0 > b1t0;
            b2t0 = q1 ? b1t0 : c2;       i2t0 = q1 ? i1t0 : j2;
            b1t0 = q1 ? sm0 : b1t0;      i1t0 = q1 ? km0 : i1t0;
        }
        {
            bool q2 = sm1 > b2t1;
            float c2 = q2 ? sm1 : b2t1;  int j2 = q2 ? km1 : i2t1;
            bool q1 = sm1 > b1t1;
            b2t1 = q1 ? b1t1 : c2;       i2t1 = q1 ? i1t1 : j2;
            b1t1 = q1 ? sm1 : b1t1;      i1t1 = q1 ? km1 : i1t1;
        }
    }
    cand_i[slice][pr][0][0] = i1t0;  cand_i[slice][pr][0][1] = i2t0;
    cand_i[slice][pr][1][0] = i1t1;  cand_i[slice][pr][1][1] = i2t1;
    __syncthreads();

    // ---- fp64 rescore of all 4 candidates per token; lowest index on ties.
    int bi0 = 0, bi1 = 0;
    #pragma unroll
    for (int tk = 0; tk < 2; tk++) {
        const float* ee = tk ? e1 : e0;
        double bscore = -DBL_MAX;
        int    bidx   = Kk;
        #pragma unroll
        for (int j = 0; j < 4; j++) {
            int kc = cand_i[j >> 1][pr][tk][j & 1];
            const float* w = buf + kc * 8;
            double dot = 0.0, nrm = 0.0;
            #pragma unroll
            for (int i = 0; i < Dd; i++) {
                double wi = (double)w[i];
                dot += (double)ee[i] * wi;
                nrm += wi * wi;
            }
            double sc = dot - 0.5 * nrm;
            if (sc > bscore || (sc == bscore && kc < bidx)) {
                bscore = sc; bidx = kc;
            }
        }
        if (tk) bi1 = bidx; else bi0 = bidx;
    }

    // ---- publish ids, then re-map to quads for phase 3
    if (slice == 0) {
        ibuf[2 * pr]     = bi0;
        ibuf[2 * pr + 1] = bi1;
    }
    __syncthreads();

    // each phase-3 thread grabs its quad's 4 codes (codebook still in buf)
    int myid[4];
    u64 qp[4][4];
    #pragma unroll
    for (int tk = 0; tk < 4; tk++) {
        myid[tk] = ibuf[4 * quad + tk];
        const ulonglong2* w = reinterpret_cast<const ulonglong2*>(buf + myid[tk] * 8);
        ulonglong2 x0 = w[0], x1 = w[1];
        qp[tk][0] = x0.x; qp[tk][1] = x0.y; qp[tk][2] = x1.x; qp[tk][3] = x1.y;
    }
    __syncthreads();   // codebook reads done

    // ---- Phase 3a: stage out_w ([C,D] already c*8+d); aux2 <- (out_b, 0)
    for (int i = tid; i < Cc * Dd; i += NT) buf[i] = out_w[i];
    for (int i = tid; i < Cc; i += NT)      aux2[i] = pk2(out_b[i], 0.0f);
    __syncthreads();

    // ---- Phase 3b: quad mapping — 4 tokens, channels [slc3*256, +256).
    float* op = out + (size_t)b * Cc * Tt + tq0;
    const int cbeg3 = slc3 * CH3;
    #pragma unroll 4
    for (int c = cbeg3; c < cbeg3 + CH3; c++) {
        const ulonglong2* wp = reinterpret_cast<const ulonglong2*>(buf + c * 8);
        ulonglong2 wA = wp[0], wB = wp[1];
        u64 ic = aux2[c];
        float s[4];
        #pragma unroll
        for (int tk = 0; tk < 4; tk++) {
            u64 dd = ffma2(qp[tk][3], wB.y, ffma2(qp[tk][2], wB.x,
                     ffma2(qp[tk][1], wA.y, ffma2(qp[tk][0], wA.x, ic))));
            float lo, hi;
            upk2(dd, lo, hi);
            s[tk] = lo + hi;
        }
        *reinterpret_cast<float4*>(op + (size_t)c * Tt) =
            make_float4(s[0], s[1], s[2], s[3]);
    }

    if (slc3 == 0 && ids_out) {
        *reinterpret_cast<float4*>(ids_out + (size_t)b * Tt + tq0) =
            make_float4((float)myid[0], (float)myid[1],
                        (float)myid[2], (float)myid[3]);
    }
}

extern "C" void kernel_launch(void* const* d_in, const int* in_sizes, int n_in,
                              void* d_out, int out_size) {
    const float* z     = (const float*)d_in[0];
    const float* in_w  = (const float*)d_in[1];
    const float* in_b  = (const float*)d_in[2];
    const float* cb    = (const float*)d_in[3];
    const float* out_w = (const float*)d_in[4];
    const float* out_b = (const float*)d_in[5];

    float* out = (float*)d_out;
    const long long out_elems = (long long)Bb * Cc * Tt;
    float* ids = (out_size > out_elems) ? out + out_elems : nullptr;

    dim3 grid(Bb * (Tt / TT));   // 256 blocks x 256 threads
    vq_fused<<<grid, NT>>>(z, in_w, in_b, cb, out_w, out_b, out, ids);
}